// round 1
// baseline (speedup 1.0000x reference)
#include <cuda_runtime.h>

typedef unsigned long long u64;

#define H      128
#define SEQ    1024
#define BATCH  512
#define MBLK   4
#define NCTAS  (BATCH / MBLK)     // 128
#define NTHR   128
#define KSMEM  104
#define KREG   (H - KSMEM)        // 24
#define XCHUNK 256
#define COUT   10

// ---- dynamic smem layout (bytes) ----
#define W_OFF    0
#define W_BYTES  (KSMEM * H * 16)          // 212992: float4 {wg,wi,wf,wo} per (k,n)
#define H2_OFF   (W_OFF + W_BYTES)
#define H2_BYTES (H * MBLK * 8)            // 4096: u64 splat-pairs {h,h}, layout [k][m]
#define XS_OFF   (H2_OFF + H2_BYTES)
#define XS_BYTES (MBLK * XCHUNK * 4)       // 4096
#define WP_OFF   (XS_OFF + XS_BYTES)
#define WP_BYTES (H * COUT * 4)            // 5120
#define SMEM_TOTAL (WP_OFF + WP_BYTES)     // 226304 <= 232448

__device__ __forceinline__ u64 pk2(float lo, float hi) {
    u64 r;
    asm("mov.b64 %0, {%1, %2};" : "=l"(r) : "f"(lo), "f"(hi));
    return r;
}
__device__ __forceinline__ void upk2(u64 v, float& lo, float& hi) {
    asm("mov.b64 {%0, %1}, %2;" : "=f"(lo), "=f"(hi) : "l"(v));
}
__device__ __forceinline__ u64 ffma2(u64 a, u64 b, u64 c) {
    u64 d;
    asm("fma.rn.f32x2 %0, %1, %2, %3;" : "=l"(d) : "l"(a), "l"(b), "l"(c));
    return d;
}

// Overflow-safe fast tanh: tanh(x) = sign(x) * (1 - 2/(exp(2|x|)+1))
// exp overflow -> inf -> 2*rcp(inf) = 0 -> 1.0 (correct saturation).
__device__ __forceinline__ float tanh_fast(float x) {
    float a = fabsf(x);
    float e = __expf(2.0f * a);
    float r = 1.0f - __fdividef(2.0f, e + 1.0f);
    return copysignf(r, x);
}
// sigmoid(x) = 1/(1+exp(-x)); exp overflow -> 0, exp underflow -> 1. Safe.
__device__ __forceinline__ float sigmoid_fast(float x) {
    float e = __expf(-x);
    return __fdividef(1.0f, 1.0f + e);
}

__global__ void __launch_bounds__(NTHR, 1)
lstm_persistent_kernel(const float* __restrict__ x,
                       const float* __restrict__ Wgx, const float* __restrict__ Wgh, const float* __restrict__ bg,
                       const float* __restrict__ Wix, const float* __restrict__ Wih, const float* __restrict__ bi,
                       const float* __restrict__ Wfx, const float* __restrict__ Wfh, const float* __restrict__ bf,
                       const float* __restrict__ Wox, const float* __restrict__ Woh, const float* __restrict__ bo,
                       const float* __restrict__ Wph, const float* __restrict__ bp,
                       float* __restrict__ out)
{
    extern __shared__ char smem[];
    float4* w4 = (float4*)(smem + W_OFF);            // [KSMEM*H] gate-packed weights
    u64 (*h2)[MBLK] = (u64(*)[MBLK])(smem + H2_OFF); // [H][MBLK] splat pairs {h,h}
    float* xs  = (float*)(smem + XS_OFF);            // [MBLK][XCHUNK]
    float* wps = (float*)(smem + WP_OFF);            // [H*COUT]

    const int n  = threadIdx.x;          // gate-column group: owns cols n, H+n, 2H+n, 3H+n
    const int m0 = blockIdx.x * MBLK;    // batch rows [m0, m0+4)

    // ---- init: weights k=0..KSMEM-1 into smem as float4 {g,i,f,o} ----
    for (int idx = n; idx < KSMEM * H; idx += NTHR) {
        int k = idx >> 7, nn = idx & (H - 1);
        float4 v;
        v.x = Wgh[k * H + nn];
        v.y = Wih[k * H + nn];
        v.z = Wfh[k * H + nn];
        v.w = Woh[k * H + nn];
        w4[idx] = v;
    }

    // ---- register-resident weights for k = KSMEM..H-1 (per-thread column n) ----
    u64 wrgi[KREG], wrfo[KREG];
#pragma unroll
    for (int r = 0; r < KREG; r++) {
        int k = KSMEM + r;
        wrgi[r] = pk2(Wgh[k * H + n], Wih[k * H + n]);
        wrfo[r] = pk2(Wfh[k * H + n], Woh[k * H + n]);
    }

    // ---- per-thread input-projection weights and biases ----
    const u64 wxgi = pk2(Wgx[n], Wix[n]);
    const u64 wxfo = pk2(Wfx[n], Wox[n]);
    u64 bgi[MBLK], bfo[MBLK];
#pragma unroll
    for (int m = 0; m < MBLK; m++) {
        bgi[m] = pk2(bg[(m0 + m) * H + n], bi[(m0 + m) * H + n]);
        bfo[m] = pk2(bf[(m0 + m) * H + n], bo[(m0 + m) * H + n]);
    }

    // ---- state init ----
#pragma unroll
    for (int m = 0; m < MBLK; m++) h2[n][m] = 0ull;
    float c[MBLK] = {0.f, 0.f, 0.f, 0.f};
    __syncthreads();

    // ---- time loop ----
    for (int t = 0; t < SEQ; t++) {
        if ((t & (XCHUNK - 1)) == 0) {
            __syncthreads();
            for (int i = n; i < MBLK * XCHUNK; i += NTHR) {
                int mm = i / XCHUNK, tt = i - mm * XCHUNK;
                xs[i] = x[(m0 + mm) * SEQ + t + tt];
            }
            __syncthreads();
        }
        const int ti = t & (XCHUNK - 1);

        // acc init: z = x*Wx + b
        u64 agi[MBLK], afo[MBLK];
#pragma unroll
        for (int m = 0; m < MBLK; m++) {
            float xv = xs[m * XCHUNK + ti];
            u64 xm = pk2(xv, xv);
            agi[m] = ffma2(xm, wxgi, bgi[m]);
            afo[m] = ffma2(xm, wxfo, bfo[m]);
        }

        // smem-weight k loop
        const ulonglong2* wp = (const ulonglong2*)w4;
#pragma unroll 8
        for (int k = 0; k < KSMEM; k++) {
            ulonglong2 w   = wp[k * H + n];                       // {wg,wi},{wf,wo}
            ulonglong2 h01 = *(const ulonglong2*)&h2[k][0];       // {h0,h0},{h1,h1}
            ulonglong2 h23 = *(const ulonglong2*)&h2[k][2];
            agi[0] = ffma2(h01.x, w.x, agi[0]);  afo[0] = ffma2(h01.x, w.y, afo[0]);
            agi[1] = ffma2(h01.y, w.x, agi[1]);  afo[1] = ffma2(h01.y, w.y, afo[1]);
            agi[2] = ffma2(h23.x, w.x, agi[2]);  afo[2] = ffma2(h23.x, w.y, afo[2]);
            agi[3] = ffma2(h23.y, w.x, agi[3]);  afo[3] = ffma2(h23.y, w.y, afo[3]);
        }
        // register-weight k loop
#pragma unroll
        for (int r = 0; r < KREG; r++) {
            int k = KSMEM + r;
            ulonglong2 h01 = *(const ulonglong2*)&h2[k][0];
            ulonglong2 h23 = *(const ulonglong2*)&h2[k][2];
            agi[0] = ffma2(h01.x, wrgi[r], agi[0]);  afo[0] = ffma2(h01.x, wrfo[r], afo[0]);
            agi[1] = ffma2(h01.y, wrgi[r], agi[1]);  afo[1] = ffma2(h01.y, wrfo[r], afo[1]);
            agi[2] = ffma2(h23.x, wrgi[r], agi[2]);  afo[2] = ffma2(h23.x, wrfo[r], afo[2]);
            agi[3] = ffma2(h23.y, wrgi[r], agi[3]);  afo[3] = ffma2(h23.y, wrfo[r], afo[3]);
        }

        // gates + state update
        float hv[MBLK];
#pragma unroll
        for (int m = 0; m < MBLK; m++) {
            float zg, zi, zf, zo;
            upk2(agi[m], zg, zi);
            upk2(afo[m], zf, zo);
            float g  = tanh_fast(zg);
            float ig = sigmoid_fast(zi);
            float fg = sigmoid_fast(zf);
            float og = sigmoid_fast(zo);
            c[m] = fmaf(g, ig, c[m] * fg);
            hv[m] = tanh_fast(c[m]) * og;
        }

        __syncthreads();   // everyone done reading old h
        {
            ulonglong2 p01, p23;
            p01.x = pk2(hv[0], hv[0]);  p01.y = pk2(hv[1], hv[1]);
            p23.x = pk2(hv[2], hv[2]);  p23.y = pk2(hv[3], hv[3]);
            *(ulonglong2*)&h2[n][0] = p01;
            *(ulonglong2*)&h2[n][2] = p23;
        }
        __syncthreads();   // new h visible
    }

    // ---- final projection: out = h @ Wph + bp ----
    for (int i = n; i < H * COUT; i += NTHR) wps[i] = Wph[i];
    __syncthreads();
    if (n < MBLK * COUT) {
        int m = n / COUT, cc = n - m * COUT;
        float s = bp[(m0 + m) * COUT + cc];
#pragma unroll 16
        for (int k = 0; k < H; k++) {
            float hk = __uint_as_float((unsigned)(h2[k][m] & 0xffffffffull));
            s = fmaf(hk, wps[k * COUT + cc], s);
        }
        out[(m0 + m) * COUT + cc] = s;
    }
}

extern "C" void kernel_launch(void* const* d_in, const int* in_sizes, int n_in,
                              void* d_out, int out_size) {
    const float* x   = (const float*)d_in[0];
    const float* Wgx = (const float*)d_in[1];
    const float* Wgh = (const float*)d_in[2];
    const float* bg  = (const float*)d_in[3];
    const float* Wix = (const float*)d_in[4];
    const float* Wih = (const float*)d_in[5];
    const float* bi  = (const float*)d_in[6];
    const float* Wfx = (const float*)d_in[7];
    const float* Wfh = (const float*)d_in[8];
    const float* bf  = (const float*)d_in[9];
    const float* Wox = (const float*)d_in[10];
    const float* Woh = (const float*)d_in[11];
    const float* bo  = (const float*)d_in[12];
    const float* Wph = (const float*)d_in[13];
    const float* bp  = (const float*)d_in[14];
    float* out = (float*)d_out;

    cudaFuncSetAttribute(lstm_persistent_kernel,
                         cudaFuncAttributeMaxDynamicSharedMemorySize, SMEM_TOTAL);

    lstm_persistent_kernel<<<NCTAS, NTHR, SMEM_TOTAL>>>(
        x, Wgx, Wgh, bg, Wix, Wih, bi, Wfx, Wfh, bf, Wox, Woh, bo, Wph, bp, out);
}

// round 2
// speedup vs baseline: 1.2686x; 1.2686x over previous
#include <cuda_runtime.h>

typedef unsigned long long u64;

#define H       128
#define SEQ     1024
#define MBLK    4
#define NCTAS   128
#define NTHR    256
#define COUT    10

#define NGROUPS 16              // 4-k groups per kh half (64 k's)
#define REG_G   8               // groups with register-resident weights
#define SMEM_G  (NGROUPS - REG_G)   // 8 groups from smem

// ---- dynamic smem layout (bytes, all 16B aligned) ----
#define WS_BYTES  (2 * SMEM_G * 4 * 128 * 16)   // 131072: ulonglong2 weight pairs
#define PB_BYTES  (4 * 128 * 16)                // 8192:  float4 partial exchange
#define XS_BYTES  (MBLK * SEQ * 4)              // 16384: all x for this CTA
#define WPS_BYTES (H * COUT * 4)                // 5120
#define HS_BYTES  (MBLK * H * 4)                // 2048
#define WS_OFF    0
#define PB_OFF    (WS_OFF + WS_BYTES)
#define XS_OFF    (PB_OFF + PB_BYTES)
#define WPS_OFF   (XS_OFF + XS_BYTES)
#define HS_OFF    (WPS_OFF + WPS_BYTES)
#define SMEM_TOTAL (HS_OFF + HS_BYTES)          // 162816

__device__ __forceinline__ u64 pk2(float lo, float hi) {
    u64 r;
    asm("mov.b64 %0, {%1, %2};" : "=l"(r) : "f"(lo), "f"(hi));
    return r;
}
__device__ __forceinline__ void upk2(u64 v, float& lo, float& hi) {
    asm("mov.b64 {%0, %1}, %2;" : "=f"(lo), "=f"(hi) : "l"(v));
}
__device__ __forceinline__ u64 ffma2(u64 a, u64 b, u64 c) {
    u64 d;
    asm("fma.rn.f32x2 %0, %1, %2, %3;" : "=l"(d) : "l"(a), "l"(b), "l"(c));
    return d;
}

// Overflow-safe fast tanh / sigmoid (proven rel_err ~3e-7 in R1).
__device__ __forceinline__ float tanh_fast(float x) {
    float a = fabsf(x);
    float e = __expf(2.0f * a);
    float r = 1.0f - __fdividef(2.0f, e + 1.0f);
    return copysignf(r, x);
}
__device__ __forceinline__ float sigmoid_fast(float x) {
    float e = __expf(-x);
    return __fdividef(1.0f, 1.0f + e);
}

__global__ void __launch_bounds__(NTHR, 1)
lstm_persistent_kernel(const float* __restrict__ x,
                       const float* __restrict__ Wgx, const float* __restrict__ Wgh, const float* __restrict__ bg,
                       const float* __restrict__ Wix, const float* __restrict__ Wih, const float* __restrict__ bi,
                       const float* __restrict__ Wfx, const float* __restrict__ Wfh, const float* __restrict__ bf,
                       const float* __restrict__ Wox, const float* __restrict__ Woh, const float* __restrict__ bo,
                       const float* __restrict__ Wph, const float* __restrict__ bp,
                       float* __restrict__ out)
{
    extern __shared__ char smem[];
    ulonglong2* ws = (ulonglong2*)(smem + WS_OFF);  // [2*SMEM_G*4][128]
    float4*     pb = (float4*)(smem + PB_OFF);      // [4][128]
    float*     xsm = (float*)(smem + XS_OFF);       // [4][SEQ]
    float*     wps = (float*)(smem + WPS_OFF);      // [H*COUT]
    float*      hs = (float*)(smem + HS_OFF);       // [4][128] plain f32

    const int tid = threadIdx.x;
    const int n   = tid & 127;            // gate-column (owns cols n, H+n, 2H+n, 3H+n)
    const int kh  = tid >> 7;             // k-half: 0 -> k[0,64), 1 -> k[64,128)
    const int khbase = kh << 6;
    const int m0  = blockIdx.x * MBLK;

    // ---- init: smem weights (8 groups per kh half), k-pair packed ----
    // ws[(sg*4+q)*128 + nn]: q0={wg_p0,wi_p0} q1={wf_p0,wo_p0} q2={wg_p1,wi_p1} q3={wf_p1,wo_p1}
    for (int i = tid; i < 2 * SMEM_G * 128; i += NTHR) {
        int sg  = i >> 7;
        int nn  = i & 127;
        int khh = sg / SMEM_G;
        int g   = REG_G + (sg - khh * SMEM_G);
        int k0  = khh * 64 + g * 4;
        ulonglong2 v;
        v.x = pk2(Wgh[(k0+0)*H+nn], Wgh[(k0+1)*H+nn]);
        v.y = pk2(Wih[(k0+0)*H+nn], Wih[(k0+1)*H+nn]);
        ws[(sg*4+0)*128 + nn] = v;
        v.x = pk2(Wfh[(k0+0)*H+nn], Wfh[(k0+1)*H+nn]);
        v.y = pk2(Woh[(k0+0)*H+nn], Woh[(k0+1)*H+nn]);
        ws[(sg*4+1)*128 + nn] = v;
        v.x = pk2(Wgh[(k0+2)*H+nn], Wgh[(k0+3)*H+nn]);
        v.y = pk2(Wih[(k0+2)*H+nn], Wih[(k0+3)*H+nn]);
        ws[(sg*4+2)*128 + nn] = v;
        v.x = pk2(Wfh[(k0+2)*H+nn], Wfh[(k0+3)*H+nn]);
        v.y = pk2(Woh[(k0+2)*H+nn], Woh[(k0+3)*H+nn]);
        ws[(sg*4+3)*128 + nn] = v;
    }

    // ---- register-resident weight groups (k-pair packed) ----
    // wreg[g][0..7] = wg_p0, wi_p0, wf_p0, wo_p0, wg_p1, wi_p1, wf_p1, wo_p1
    u64 wreg[REG_G][8];
#pragma unroll
    for (int g = 0; g < REG_G; g++) {
        int k0 = khbase + g * 4;
        wreg[g][0] = pk2(Wgh[(k0+0)*H+n], Wgh[(k0+1)*H+n]);
        wreg[g][1] = pk2(Wih[(k0+0)*H+n], Wih[(k0+1)*H+n]);
        wreg[g][2] = pk2(Wfh[(k0+0)*H+n], Wfh[(k0+1)*H+n]);
        wreg[g][3] = pk2(Woh[(k0+0)*H+n], Woh[(k0+1)*H+n]);
        wreg[g][4] = pk2(Wgh[(k0+2)*H+n], Wgh[(k0+3)*H+n]);
        wreg[g][5] = pk2(Wih[(k0+2)*H+n], Wih[(k0+3)*H+n]);
        wreg[g][6] = pk2(Wfh[(k0+2)*H+n], Wfh[(k0+3)*H+n]);
        wreg[g][7] = pk2(Woh[(k0+2)*H+n], Woh[(k0+3)*H+n]);
    }

    // ---- per-thread x-weights and biases for the 2 owned rows ----
    const float wxg = Wgx[n], wxi = Wix[n], wxf = Wfx[n], wxo = Wox[n];
    const int gm0 = kh * 2, gm1 = kh * 2 + 1;
    const float bG0 = bg[(m0+gm0)*H+n], bI0 = bi[(m0+gm0)*H+n];
    const float bF0 = bf[(m0+gm0)*H+n], bO0 = bo[(m0+gm0)*H+n];
    const float bG1 = bg[(m0+gm1)*H+n], bI1 = bi[(m0+gm1)*H+n];
    const float bF1 = bf[(m0+gm1)*H+n], bO1 = bo[(m0+gm1)*H+n];

    // ---- x (all steps for 4 rows), Wph, h init ----
    for (int i = tid; i < MBLK * SEQ; i += NTHR) {
        int mm = i >> 10, tt = i & (SEQ - 1);
        xsm[i] = x[(m0+mm)*SEQ + tt];
    }
    for (int i = tid; i < H * COUT; i += NTHR) wps[i] = Wph[i];
    for (int i = tid; i < MBLK * H; i += NTHR) hs[i] = 0.0f;
    float c0 = 0.0f, c1 = 0.0f;
    __syncthreads();

    // ---- time loop ----
    for (int t = 0; t < SEQ; t++) {
        // acc[gate][m] = f32x2 pair accumulating even/odd-k partial sums
        u64 acc[4][4];
#pragma unroll
        for (int g4 = 0; g4 < 4; g4++)
#pragma unroll
            for (int m = 0; m < 4; m++) acc[g4][m] = 0ull;

#pragma unroll
        for (int g = 0; g < NGROUPS; g++) {
            u64 wp0, wp1, wp2, wp3, wp4, wp5, wp6, wp7;
            if (g < REG_G) {
                wp0 = wreg[g][0]; wp1 = wreg[g][1]; wp2 = wreg[g][2]; wp3 = wreg[g][3];
                wp4 = wreg[g][4]; wp5 = wreg[g][5]; wp6 = wreg[g][6]; wp7 = wreg[g][7];
            } else {
                int sg = kh * SMEM_G + (g - REG_G);
                ulonglong2 a0 = ws[(sg*4+0)*128 + n];
                ulonglong2 a1 = ws[(sg*4+1)*128 + n];
                ulonglong2 a2 = ws[(sg*4+2)*128 + n];
                ulonglong2 a3 = ws[(sg*4+3)*128 + n];
                wp0 = a0.x; wp1 = a0.y; wp2 = a1.x; wp3 = a1.y;
                wp4 = a2.x; wp5 = a2.y; wp6 = a3.x; wp7 = a3.y;
            }
            const int kbase = khbase + (g << 2);
#pragma unroll
            for (int m = 0; m < 4; m++) {
                // {h[k],h[k+1]}, {h[k+2],h[k+3]} straight from plain-f32 h (broadcast)
                ulonglong2 hu = *(const ulonglong2*)(hs + (m << 7) + kbase);
                acc[0][m] = ffma2(hu.x, wp0, acc[0][m]);
                acc[1][m] = ffma2(hu.x, wp1, acc[1][m]);
                acc[2][m] = ffma2(hu.x, wp2, acc[2][m]);
                acc[3][m] = ffma2(hu.x, wp3, acc[3][m]);
                acc[0][m] = ffma2(hu.y, wp4, acc[0][m]);
                acc[1][m] = ffma2(hu.y, wp5, acc[1][m]);
                acc[2][m] = ffma2(hu.y, wp6, acc[2][m]);
                acc[3][m] = ffma2(hu.y, wp7, acc[3][m]);
            }
        }

        // reduce pairs -> scalar partials
        float part[4][4];
#pragma unroll
        for (int g4 = 0; g4 < 4; g4++)
#pragma unroll
            for (int m = 0; m < 4; m++) {
                float lo, hi;
                upk2(acc[g4][m], lo, hi);
                part[g4][m] = lo + hi;
            }

        // send partials for the OTHER half's rows
        {
            int om = (1 - kh) * 2;
            pb[(kh*2+0)*128 + n] = make_float4(part[0][om],   part[1][om],   part[2][om],   part[3][om]);
            pb[(kh*2+1)*128 + n] = make_float4(part[0][om+1], part[1][om+1], part[2][om+1], part[3][om+1]);
        }
        __syncthreads();   // partials visible; all old-h reads complete
        float4 r0 = pb[((1-kh)*2+0)*128 + n];
        float4 r1 = pb[((1-kh)*2+1)*128 + n];

        // gates for the 2 owned rows
        {
            float xv = xsm[gm0*SEQ + t];
            float zg = part[0][gm0] + r0.x + fmaf(xv, wxg, bG0);
            float zi = part[1][gm0] + r0.y + fmaf(xv, wxi, bI0);
            float zf = part[2][gm0] + r0.z + fmaf(xv, wxf, bF0);
            float zo = part[3][gm0] + r0.w + fmaf(xv, wxo, bO0);
            float gg = tanh_fast(zg);
            float ii = sigmoid_fast(zi);
            float ff = sigmoid_fast(zf);
            float oo = sigmoid_fast(zo);
            c0 = fmaf(gg, ii, c0 * ff);
            hs[gm0*128 + n] = tanh_fast(c0) * oo;
        }
        {
            float xv = xsm[gm1*SEQ + t];
            float zg = part[0][gm1] + r1.x + fmaf(xv, wxg, bG1);
            float zi = part[1][gm1] + r1.y + fmaf(xv, wxi, bI1);
            float zf = part[2][gm1] + r1.z + fmaf(xv, wxf, bF1);
            float zo = part[3][gm1] + r1.w + fmaf(xv, wxo, bO1);
            float gg = tanh_fast(zg);
            float ii = sigmoid_fast(zi);
            float ff = sigmoid_fast(zf);
            float oo = sigmoid_fast(zo);
            c1 = fmaf(gg, ii, c1 * ff);
            hs[gm1*128 + n] = tanh_fast(c1) * oo;
        }
        __syncthreads();   // new h visible for next step
    }

    // ---- final projection: out = h @ Wph + bp ----
    if (tid < MBLK * COUT) {
        int m = tid / COUT, cc = tid - m * COUT;
        float s = bp[(m0+m)*COUT + cc];
#pragma unroll 16
        for (int k = 0; k < H; k++)
            s = fmaf(hs[m*128 + k], wps[k*COUT + cc], s);
        out[(m0+m)*COUT + cc] = s;
    }
}

extern "C" void kernel_launch(void* const* d_in, const int* in_sizes, int n_in,
                              void* d_out, int out_size) {
    const float* x   = (const float*)d_in[0];
    const float* Wgx = (const float*)d_in[1];
    const float* Wgh = (const float*)d_in[2];
    const float* bg  = (const float*)d_in[3];
    const float* Wix = (const float*)d_in[4];
    const float* Wih = (const float*)d_in[5];
    const float* bi  = (const float*)d_in[6];
    const float* Wfx = (const float*)d_in[7];
    const float* Wfh = (const float*)d_in[8];
    const float* bf  = (const float*)d_in[9];
    const float* Wox = (const float*)d_in[10];
    const float* Woh = (const float*)d_in[11];
    const float* bo  = (const float*)d_in[12];
    const float* Wph = (const float*)d_in[13];
    const float* bp  = (const float*)d_in[14];
    float* out = (float*)d_out;

    cudaFuncSetAttribute(lstm_persistent_kernel,
                         cudaFuncAttributeMaxDynamicSharedMemorySize, SMEM_TOTAL);

    lstm_persistent_kernel<<<NCTAS, NTHR, SMEM_TOTAL>>>(
        x, Wgx, Wgh, bg, Wix, Wih, bi, Wfx, Wfh, bf, Wox, Woh, bo, Wph, bp, out);
}